// round 14
// baseline (speedup 1.0000x reference)
#include <cuda_runtime.h>
#include <cuda_bf16.h>
#include <cuda_fp16.h>
#include <cstddef>
#include <cstdint>

#define N_NODES 50000
#define E_MAX   1700000
#define W_TOTAL 573440
#define FEAT_N  (N_NODES * 512)

// ---------------- scratch (device globals; no runtime allocation) ------------
__device__ __half g_y[(size_t)N_NODES * 384];   // fp16 GEMM outputs
__device__ __half g_x[(size_t)N_NODES * 512];   // fp16 activations (GEMM A operand)
__device__ __half g_w[W_TOTAL];                 // fp16 weights
__device__ int   g_row_ptr[N_NODES + 1];
__device__ int   g_col[E_MAX];
__device__ int   g_cursor[N_NODES];
__device__ int   g_in_deg[N_NODES];
__device__ int   g_out_deg[N_NODES];
__device__ float g_inv_den[N_NODES];
__device__ float g_inv_src[N_NODES];
__device__ float g_inv_dst[N_NODES];

// ---------------- helpers -----------------------------------------------------
__device__ __forceinline__ uint32_t smem_u32(const void* p) {
    uint32_t a;
    asm("{ .reg .u64 t; cvta.to.shared.u64 t, %1; cvt.u32.u64 %0, t; }" : "=r"(a) : "l"(p));
    return a;
}
__device__ __forceinline__ void ldsm4(uint32_t* r, uint32_t addr) {
    asm volatile("ldmatrix.sync.aligned.m8n8.x4.shared.b16 {%0,%1,%2,%3}, [%4];"
        : "=r"(r[0]), "=r"(r[1]), "=r"(r[2]), "=r"(r[3]) : "r"(addr));
}
__device__ __forceinline__ void mma16816h(float* c, const uint32_t* a, const uint32_t* b) {
    asm volatile("mma.sync.aligned.m16n8k16.row.col.f32.f16.f16.f32 "
        "{%0,%1,%2,%3}, {%4,%5,%6,%7}, {%8,%9}, {%0,%1,%2,%3};"
        : "+f"(c[0]), "+f"(c[1]), "+f"(c[2]), "+f"(c[3])
        : "r"(a[0]), "r"(a[1]), "r"(a[2]), "r"(a[3]), "r"(b[0]), "r"(b[1]));
}
__device__ __forceinline__ void cp16(uint32_t smem, const void* g, int srcsz) {
    asm volatile("cp.async.cg.shared.global [%0], [%1], 16, %2;"
        :: "r"(smem), "l"(g), "r"(srcsz) : "memory");
}

// ---------------- CSR construction ------------------------------------------
__global__ void k_zero_deg() {
    int i = blockIdx.x * blockDim.x + threadIdx.x;
    if (i < N_NODES) { g_in_deg[i] = 0; g_out_deg[i] = 0; }
}

__global__ void k_count(const int* __restrict__ src, const int* __restrict__ dst, int E) {
    int e4 = (blockIdx.x * blockDim.x + threadIdx.x) * 4;
    if (e4 + 3 < E) {
        int4 s = *(const int4*)(src + e4);
        int4 d = *(const int4*)(dst + e4);
        atomicAdd(&g_in_deg[d.x], 1); atomicAdd(&g_in_deg[d.y], 1);
        atomicAdd(&g_in_deg[d.z], 1); atomicAdd(&g_in_deg[d.w], 1);
        atomicAdd(&g_out_deg[s.x], 1); atomicAdd(&g_out_deg[s.y], 1);
        atomicAdd(&g_out_deg[s.z], 1); atomicAdd(&g_out_deg[s.w], 1);
    } else {
        for (int e = e4; e < E; ++e) {
            atomicAdd(&g_in_deg[dst[e]], 1);
            atomicAdd(&g_out_deg[src[e]], 1);
        }
    }
}

// scan over in_deg -> row_ptr, fused scalers/cursor epilogue
__global__ void k_scan() {
    __shared__ int wsum[32];
    __shared__ int carry;
    const int tid  = threadIdx.x;
    const int lane = tid & 31;
    const int w    = tid >> 5;
    if (tid == 0) { carry = 0; g_row_ptr[0] = 0; }
    __syncthreads();
    for (int base = 0; base < N_NODES; base += 1024) {
        int idx = base + tid;
        int v = (idx < N_NODES) ? g_in_deg[idx] : 0;
        int x = v;
#pragma unroll
        for (int off = 1; off < 32; off <<= 1) {
            int t = __shfl_up_sync(0xffffffffu, x, off);
            if (lane >= off) x += t;
        }
        if (lane == 31) wsum[w] = x;
        __syncthreads();
        if (w == 0) {
            int s = wsum[lane];
#pragma unroll
            for (int off = 1; off < 32; off <<= 1) {
                int t = __shfl_up_sync(0xffffffffu, s, off);
                if (lane >= off) s += t;
            }
            wsum[lane] = s;
        }
        __syncthreads();
        int total  = wsum[31];
        int prefix = carry + (w > 0 ? wsum[w - 1] : 0) + x;  // inclusive
        if (idx < N_NODES) {
            g_row_ptr[idx + 1] = prefix;
            g_cursor[idx]      = prefix - v;                 // exclusive = row start
            g_inv_den[idx]     = 1.0f / (float)(v + 1);
            g_inv_dst[idx]     = rsqrtf((float)(v > 0 ? v : 1));
            int od = g_out_deg[idx];
            g_inv_src[idx]     = rsqrtf((float)(od > 0 ? od : 1));
        }
        __syncthreads();
        if (tid == 0) carry += total;
        __syncthreads();
    }
}

__global__ void k_fill(const int* __restrict__ src, const int* __restrict__ dst, int E) {
    int e4 = (blockIdx.x * blockDim.x + threadIdx.x) * 4;
    if (e4 + 3 < E) {
        int4 s = *(const int4*)(src + e4);
        int4 d = *(const int4*)(dst + e4);
        g_col[atomicAdd(&g_cursor[d.x], 1)] = s.x;
        g_col[atomicAdd(&g_cursor[d.y], 1)] = s.y;
        g_col[atomicAdd(&g_cursor[d.z], 1)] = s.z;
        g_col[atomicAdd(&g_cursor[d.w], 1)] = s.w;
    } else {
        for (int e = e4; e < E; ++e)
            g_col[atomicAdd(&g_cursor[dst[e]], 1)] = src[e];
    }
}

// ---------------- fused converter (features + weights -> fp16) ----------------
struct ConvArgs { const float* feat; const float* w[7]; };

__global__ void k_convert_all(ConvArgs a) {
    int i = blockIdx.x * blockDim.x + threadIdx.x;
    if (i < FEAT_N) {
        g_x[i] = __float2half_rn(a.feat[i]);
        return;
    }
    int j = i - FEAT_N;
    if (j >= W_TOTAL) return;
    const int starts[7] = {0, 196608, 344064, 442368, 507904, 540672, 557056};
    int seg = 0;
#pragma unroll
    for (int k = 1; k < 7; ++k) seg += (j >= starts[k]) ? 1 : 0;
    g_w[j] = __float2half_rn(a.w[seg][j - starts[seg]]);
}

// ---------------- aggregation: one WARP per dst node, wide fp16 gathers ------
// GC=false (SAGE): out_i = relu((sum y_s + y_i) * inv_den_i + b)
// GC=true  (GCN) : out_i = relu(inv_dst_i * sum y'_s + b),  y' = inv_src*y
template <int DIM, bool GC>
__global__ void k_agg(const __half* __restrict__ y, __half* __restrict__ x,
                      const float* __restrict__ bias) {
    const int gwarp = (blockIdx.x * blockDim.x + threadIdx.x) >> 5;
    if (gwarp >= N_NODES) return;
    const int lane = threadIdx.x & 31;
    constexpr bool H8 = (DIM >= 256);
    constexpr bool H4 = (DIM == 384) || (DIM == 128);
    constexpr int  B4 = (DIM == 384) ? 256 : 0;

    float a8[H8 ? 8 : 1];
    float a4[H4 ? 4 : 1];
#pragma unroll
    for (int q = 0; q < (H8 ? 8 : 1); ++q) a8[q] = 0.f;
#pragma unroll
    for (int q = 0; q < (H4 ? 4 : 1); ++q) a4[q] = 0.f;

    const int start = g_row_ptr[gwarp];
    const int end   = g_row_ptr[gwarp + 1];

    auto accum_row = [&](int s) {
        const __half* yr = y + (size_t)s * DIM;
        if (H8) {
            uint4 v = *(const uint4*)(yr + lane * 8);
            const __half2* p = (const __half2*)&v;
#pragma unroll
            for (int q = 0; q < 4; ++q) {
                float2 f = __half22float2(p[q]);
                a8[q * 2]     += f.x;
                a8[q * 2 + 1] += f.y;
            }
        }
        if (H4) {
            uint2 v = *(const uint2*)(yr + B4 + lane * 4);
            const __half2* p = (const __half2*)&v;
#pragma unroll
            for (int q = 0; q < 2; ++q) {
                float2 f = __half22float2(p[q]);
                a4[q * 2]     += f.x;
                a4[q * 2 + 1] += f.y;
            }
        }
    };

    int e = start;
    for (; e + 3 < end; e += 4) {      // 4-way unroll: deeper gather MLP
        const int s0 = g_col[e];
        const int s1 = g_col[e + 1];
        const int s2 = g_col[e + 2];
        const int s3 = g_col[e + 3];
        accum_row(s0);
        accum_row(s1);
        accum_row(s2);
        accum_row(s3);
    }
    for (; e < end; ++e) accum_row(g_col[e]);

    __half* xr = x + (size_t)gwarp * DIM;
    const __half* yi = y + (size_t)gwarp * DIM;
    const float wsc = GC ? g_inv_dst[gwarp] : g_inv_den[gwarp];

    if (H8) {
        float o[8];
        if (GC) {
#pragma unroll
            for (int q = 0; q < 8; ++q)
                o[q] = fmaxf(a8[q] * wsc + bias[lane * 8 + q], 0.f);
        } else {
            uint4 v = *(const uint4*)(yi + lane * 8);
            const __half2* p = (const __half2*)&v;
#pragma unroll
            for (int q = 0; q < 4; ++q) {
                float2 f = __half22float2(p[q]);
                o[q * 2]     = fmaxf((a8[q * 2]     + f.x) * wsc + bias[lane * 8 + q * 2],     0.f);
                o[q * 2 + 1] = fmaxf((a8[q * 2 + 1] + f.y) * wsc + bias[lane * 8 + q * 2 + 1], 0.f);
            }
        }
        __half2 pk[4];
#pragma unroll
        for (int q = 0; q < 4; ++q) pk[q] = __floats2half2_rn(o[q * 2], o[q * 2 + 1]);
        *(uint4*)(xr + lane * 8) = *(const uint4*)pk;
    }
    if (H4) {
        float o[4];
        if (GC) {
#pragma unroll
            for (int q = 0; q < 4; ++q)
                o[q] = fmaxf(a4[q] * wsc + bias[B4 + lane * 4 + q], 0.f);
        } else {
            uint2 v = *(const uint2*)(yi + B4 + lane * 4);
            const __half2* p = (const __half2*)&v;
#pragma unroll
            for (int q = 0; q < 2; ++q) {
                float2 f = __half22float2(p[q]);
                o[q * 2]     = fmaxf((a4[q * 2]     + f.x) * wsc + bias[B4 + lane * 4 + q * 2],     0.f);
                o[q * 2 + 1] = fmaxf((a4[q * 2 + 1] + f.y) * wsc + bias[B4 + lane * 4 + q * 2 + 1], 0.f);
            }
        }
        __half2 pk[2];
#pragma unroll
        for (int q = 0; q < 2; ++q) pk[q] = __floats2half2_rn(o[q * 2], o[q * 2 + 1]);
        *(uint2*)(xr + B4 + lane * 4) = *(const uint2*)pk;
    }
}

// ---------------- plain fp16 HMMA GEMM (templated M-tile) ----------------------
// C = A[M,K] @ W[Nc,K]^T (fp32 accum). MT=128: 2 CTA/SM. MT=64: 3 CTA/SM,
// used for Nc=128 launches (small grid -> tail-dominated at MT=128).
// 3-stage cp.async pipeline, ONE __syncthreads per k-chunk.
template <int MT>
__global__ __launch_bounds__(256, (MT == 128) ? 2 : 3)
void k_gemm_mma(const __half* __restrict__ A, const __half* __restrict__ W,
                const float* __restrict__ bias, const float* __restrict__ rowscale,
                __half* __restrict__ Ch, float* __restrict__ Cf, int M, int K, int Nc) {
    constexpr int T_B = MT * 128;               // A tile bytes
    constexpr int STAGE = MT * 128 + 16384;     // A + B
    constexpr int MI = MT / 32;                 // m16 frags per warp
    extern __shared__ char sm[];
    const uint32_t sb = smem_u32(sm);
    const int tid  = threadIdx.x;
    const int wid  = tid >> 5;
    const int lane = tid & 31;
    const int wm = wid >> 2;
    const int wn = wid & 3;
    const int m0 = blockIdx.y * MT;
    const int n0 = blockIdx.x * 128;

    float acc[MI][4][4];
#pragma unroll
    for (int i = 0; i < MI; ++i)
#pragma unroll
        for (int j = 0; j < 4; ++j)
#pragma unroll
            for (int q = 0; q < 4; ++q) acc[i][j][q] = 0.f;

    const int nch = K >> 6;

    auto issue = [&](int ch) {
        const uint32_t so = sb + (uint32_t)(ch % 3) * STAGE;
        const int kc0 = ch << 6;
#pragma unroll
        for (int it = 0; it < MT / 32; ++it) {   // A: MT*8 cp16 over 256 thr
            const int idx = tid + it * 256;
            const int r = idx >> 3, c = idx & 7;
            const uint32_t sw = (uint32_t)(r * 128 + (((c ^ (r & 7)) & 7) << 4));
            const int gr = m0 + r;
            const int av = (gr < M) ? 16 : 0;
            cp16(so + sw, A + (size_t)gr * K + kc0 + c * 8, av);
        }
#pragma unroll
        for (int it = 0; it < 4; ++it) {         // B: 1024 cp16
            const int idx = tid + it * 256;
            const int r = idx >> 3, c = idx & 7;
            const uint32_t sw = (uint32_t)(r * 128 + (((c ^ (r & 7)) & 7) << 4));
            cp16(so + T_B + sw, W + (size_t)(n0 + r) * K + kc0 + c * 8, 16);
        }
        asm volatile("cp.async.commit_group;" ::: "memory");
    };

    issue(0);
    if (nch > 1) issue(1);

    for (int ch = 0; ch < nch; ++ch) {
        if (ch + 2 <= nch) {
            asm volatile("cp.async.wait_group 1;" ::: "memory");
        } else {
            asm volatile("cp.async.wait_group 0;" ::: "memory");
        }
        __syncthreads();   // single barrier per chunk (3-stage safety)

        const uint32_t so = sb + (uint32_t)(ch % 3) * STAGE;
#pragma unroll
        for (int kk = 0; kk < 64; kk += 16) {
            uint32_t af[MI][4];
            const int ar = (lane & 15);
            const int akb = kk + ((lane >> 4) << 3);
#pragma unroll
            for (int mi = 0; mi < MI; ++mi) {
                const int r = wm * (MT / 2) + mi * 16 + ar;
                const uint32_t off = (uint32_t)(r * 128 + ((((akb >> 3) ^ (r & 7)) & 7) << 4));
                ldsm4(af[mi], so + off);
            }
            uint32_t bf[2][4];
            const int br = ((lane >> 4) << 3) + (lane & 7);
            const int bkb = kk + (((lane >> 3) & 1) << 3);
#pragma unroll
            for (int p = 0; p < 2; ++p) {
                const int r = wn * 32 + p * 16 + br;
                const uint32_t off = (uint32_t)(r * 128 + ((((bkb >> 3) ^ (r & 7)) & 7) << 4));
                ldsm4(bf[p], so + T_B + off);
            }
#pragma unroll
            for (int mi = 0; mi < MI; ++mi) {
#pragma unroll
                for (int j = 0; j < 4; ++j) {
                    mma16816h(acc[mi][j], af[mi], &bf[j >> 1][(j & 1) * 2]);
                }
            }
        }

        if (ch + 2 < nch) issue(ch + 2);
    }

    // ---- epilogue ----
    const int gid  = lane >> 2;
    const int tidx = lane & 3;
#pragma unroll
    for (int mi = 0; mi < MI; ++mi) {
        const int row = m0 + wm * (MT / 2) + mi * 16 + gid;
        float sc0 = 1.f, sc1 = 1.f;
        if (rowscale) {
            if (row < M)     sc0 = rowscale[row];
            if (row + 8 < M) sc1 = rowscale[row + 8];
        }
#pragma unroll
        for (int j = 0; j < 4; ++j) {
            const int col = n0 + wn * 32 + j * 8 + tidx * 2;
            if (Ch) {
                if (row < M)
                    *(__half2*)(Ch + (size_t)row * Nc + col) =
                        __floats2half2_rn(acc[mi][j][0] * sc0, acc[mi][j][1] * sc0);
                if (row + 8 < M)
                    *(__half2*)(Ch + (size_t)(row + 8) * Nc + col) =
                        __floats2half2_rn(acc[mi][j][2] * sc1, acc[mi][j][3] * sc1);
            } else {
                float b0 = 0.f, b1 = 0.f;
                if (bias) { b0 = bias[col]; b1 = bias[col + 1]; }
                if (row < M)
                    *(float2*)(Cf + (size_t)row * Nc + col) =
                        make_float2(acc[mi][j][0] + b0, acc[mi][j][1] + b1);
                if (row + 8 < M)
                    *(float2*)(Cf + (size_t)(row + 8) * Nc + col) =
                        make_float2(acc[mi][j][2] + b0, acc[mi][j][3] + b1);
            }
        }
    }
}

#define SMEM_128 ((128 * 128 + 16384) * 3)
#define SMEM_64  ((64 * 128 + 16384) * 3)

// ---------------- host orchestration -----------------------------------------
static inline void launch_gemm_h(const __half* A, const __half* w,
                                 const float* rowscale, __half* Ch, int K, int Nc) {
    if (Nc == 128) {
        dim3 grid(1, (N_NODES + 63) / 64);
        k_gemm_mma<64><<<grid, 256, SMEM_64>>>(A, w, nullptr, rowscale, Ch, nullptr,
                                               N_NODES, K, Nc);
    } else {
        dim3 grid(Nc / 128, (N_NODES + 127) / 128);
        k_gemm_mma<128><<<grid, 256, SMEM_128>>>(A, w, nullptr, rowscale, Ch, nullptr,
                                                 N_NODES, K, Nc);
    }
}
static inline void launch_gemm_f(const __half* A, const __half* w,
                                 const float* b, float* Cf, int K, int Nc) {
    dim3 grid(1, (N_NODES + 63) / 64);
    k_gemm_mma<64><<<grid, 256, SMEM_64>>>(A, w, b, nullptr, nullptr, Cf,
                                           N_NODES, K, Nc);
}

template <int DIM, bool GC>
static inline void launch_agg(const __half* y, __half* x, const float* bias) {
    int blocks = (N_NODES + 7) / 8;
    k_agg<DIM, GC><<<blocks, 256>>>(y, x, bias);
}

extern "C" void kernel_launch(void* const* d_in, const int* in_sizes, int n_in,
                              void* d_out, int out_size) {
    const float* features = (const float*)d_in[0];
    const int*   src      = (const int*)d_in[1];
    const int*   dst      = (const int*)d_in[2];
    const float* sw0 = (const float*)d_in[3];  const float* sb0 = (const float*)d_in[4];
    const float* gw0 = (const float*)d_in[5];  const float* gb0 = (const float*)d_in[6];
    const float* sw1 = (const float*)d_in[7];  const float* sb1 = (const float*)d_in[8];
    const float* gw1 = (const float*)d_in[9];  const float* gb1 = (const float*)d_in[10];
    const float* sw2 = (const float*)d_in[11]; const float* sb2 = (const float*)d_in[12];
    const float* gw2 = (const float*)d_in[13]; const float* gb2 = (const float*)d_in[14];
    const float* fcw = (const float*)d_in[15]; const float* fcb = (const float*)d_in[16];
    const int E = in_sizes[1];

    cudaFuncSetAttribute(k_gemm_mma<128>, cudaFuncAttributeMaxDynamicSharedMemorySize, SMEM_128);
    cudaFuncSetAttribute(k_gemm_mma<64>,  cudaFuncAttributeMaxDynamicSharedMemorySize, SMEM_64);

    __half *ybuf = nullptr, *xbuf = nullptr, *wbuf = nullptr;
    float* inv_src = nullptr;
    cudaGetSymbolAddress((void**)&ybuf, g_y);
    cudaGetSymbolAddress((void**)&xbuf, g_x);
    cudaGetSymbolAddress((void**)&wbuf, g_w);
    cudaGetSymbolAddress((void**)&inv_src, g_inv_src);

    const int O_SW0 = 0,      O_GW0 = 196608, O_SW1 = 344064, O_GW1 = 442368;
    const int O_SW2 = 507904, O_GW2 = 540672, O_FC  = 557056;

    // ---- CSR build ----
    k_zero_deg<<<(N_NODES + 255) / 256, 256>>>();
    k_count<<<((E + 3) / 4 + 255) / 256, 256>>>(src, dst, E);
    k_scan<<<1, 1024>>>();
    k_fill<<<((E + 3) / 4 + 255) / 256, 256>>>(src, dst, E);

    // ---- fused converts ----
    ConvArgs ca;
    ca.feat = features;
    ca.w[0] = sw0; ca.w[1] = gw0; ca.w[2] = sw1; ca.w[3] = gw1;
    ca.w[4] = sw2; ca.w[5] = gw2; ca.w[6] = fcw;
    k_convert_all<<<(FEAT_N + W_TOTAL + 255) / 256, 256>>>(ca);

    // ---- stage 0: 512 -> 384 ----
    launch_gemm_h(xbuf, wbuf + O_SW0, nullptr, ybuf, 512, 384);
    launch_agg<384, false>(ybuf, xbuf, sb0);
    launch_gemm_h(xbuf, wbuf + O_GW0, inv_src, ybuf, 384, 384);
    launch_agg<384, true>(ybuf, xbuf, gb0);

    // ---- stage 1: 384 -> 256 ----
    launch_gemm_h(xbuf, wbuf + O_SW1, nullptr, ybuf, 384, 256);
    launch_agg<256, false>(ybuf, xbuf, sb1);
    launch_gemm_h(xbuf, wbuf + O_GW1, inv_src, ybuf, 256, 256);
    launch_agg<256, true>(ybuf, xbuf, gb1);

    // ---- stage 2: 256 -> 128 ----
    launch_gemm_h(xbuf, wbuf + O_SW2, nullptr, ybuf, 256, 128);
    launch_agg<128, false>(ybuf, xbuf, sb2);
    launch_gemm_h(xbuf, wbuf + O_GW2, inv_src, ybuf, 128, 128);
    launch_agg<128, true>(ybuf, xbuf, gb2);

    // ---- final FC: 128 -> 128 (fp32 out, bias, no relu) ----
    launch_gemm_f(xbuf, wbuf + O_FC, fcb, (float*)d_out, 128, 128);
}

// round 15
// speedup vs baseline: 1.0234x; 1.0234x over previous
#include <cuda_runtime.h>
#include <cuda_bf16.h>
#include <cuda_fp16.h>
#include <cstddef>
#include <cstdint>

#define N_NODES 50000
#define E_MAX   1700000
#define W_TOTAL 573440
#define FEAT_N  (N_NODES * 512)

// ---------------- PDL primitives ---------------------------------------------
#define GRID_WAIT()    asm volatile("griddepcontrol.wait;" ::: "memory")
#define GRID_TRIGGER() asm volatile("griddepcontrol.launch_dependents;" ::: "memory")

// ---------------- scratch (device globals; no runtime allocation) ------------
__device__ __half g_y[(size_t)N_NODES * 384];   // fp16 GEMM outputs
__device__ __half g_x[(size_t)N_NODES * 512];   // fp16 activations (GEMM A operand)
__device__ __half g_w[W_TOTAL];                 // fp16 weights
__device__ int   g_row_ptr[N_NODES + 1];
__device__ int   g_col[E_MAX];
__device__ int   g_cursor[N_NODES];
__device__ int   g_in_deg[N_NODES];
__device__ int   g_out_deg[N_NODES];
__device__ float g_inv_den[N_NODES];
__device__ float g_inv_src[N_NODES];
__device__ float g_inv_dst[N_NODES];

// ---------------- helpers -----------------------------------------------------
__device__ __forceinline__ uint32_t smem_u32(const void* p) {
    uint32_t a;
    asm("{ .reg .u64 t; cvta.to.shared.u64 t, %1; cvt.u32.u64 %0, t; }" : "=r"(a) : "l"(p));
    return a;
}
__device__ __forceinline__ void ldsm4(uint32_t* r, uint32_t addr) {
    asm volatile("ldmatrix.sync.aligned.m8n8.x4.shared.b16 {%0,%1,%2,%3}, [%4];"
        : "=r"(r[0]), "=r"(r[1]), "=r"(r[2]), "=r"(r[3]) : "r"(addr));
}
__device__ __forceinline__ void mma16816h(float* c, const uint32_t* a, const uint32_t* b) {
    asm volatile("mma.sync.aligned.m16n8k16.row.col.f32.f16.f16.f32 "
        "{%0,%1,%2,%3}, {%4,%5,%6,%7}, {%8,%9}, {%0,%1,%2,%3};"
        : "+f"(c[0]), "+f"(c[1]), "+f"(c[2]), "+f"(c[3])
        : "r"(a[0]), "r"(a[1]), "r"(a[2]), "r"(a[3]), "r"(b[0]), "r"(b[1]));
}
__device__ __forceinline__ void cp16(uint32_t smem, const void* g, int srcsz) {
    asm volatile("cp.async.cg.shared.global [%0], [%1], 16, %2;"
        :: "r"(smem), "l"(g), "r"(srcsz) : "memory");
}

// ---------------- CSR construction ------------------------------------------
__global__ void k_zero_deg() {
    GRID_WAIT();
    int i = blockIdx.x * blockDim.x + threadIdx.x;
    if (i < N_NODES) { g_in_deg[i] = 0; g_out_deg[i] = 0; }
}

__global__ void k_count(const int* __restrict__ src, const int* __restrict__ dst, int E) {
    GRID_WAIT();
    int e = blockIdx.x * blockDim.x + threadIdx.x;
    if (e < E) {
        atomicAdd(&g_in_deg[dst[e]], 1);
        atomicAdd(&g_out_deg[src[e]], 1);
    }
}

// scan over in_deg -> row_ptr, fused scalers/cursor epilogue
__global__ void k_scan() {
    GRID_WAIT();
    __shared__ int wsum[32];
    __shared__ int carry;
    const int tid  = threadIdx.x;
    const int lane = tid & 31;
    const int w    = tid >> 5;
    if (tid == 0) { carry = 0; g_row_ptr[0] = 0; }
    __syncthreads();
    for (int base = 0; base < N_NODES; base += 1024) {
        int idx = base + tid;
        int v = (idx < N_NODES) ? g_in_deg[idx] : 0;
        int x = v;
#pragma unroll
        for (int off = 1; off < 32; off <<= 1) {
            int t = __shfl_up_sync(0xffffffffu, x, off);
            if (lane >= off) x += t;
        }
        if (lane == 31) wsum[w] = x;
        __syncthreads();
        if (w == 0) {
            int s = wsum[lane];
#pragma unroll
            for (int off = 1; off < 32; off <<= 1) {
                int t = __shfl_up_sync(0xffffffffu, s, off);
                if (lane >= off) s += t;
            }
            wsum[lane] = s;
        }
        __syncthreads();
        int total  = wsum[31];
        int prefix = carry + (w > 0 ? wsum[w - 1] : 0) + x;  // inclusive
        if (idx < N_NODES) {
            g_row_ptr[idx + 1] = prefix;
            g_cursor[idx]      = prefix - v;                 // exclusive = row start
            g_inv_den[idx]     = 1.0f / (float)(v + 1);
            g_inv_dst[idx]     = rsqrtf((float)(v > 0 ? v : 1));
            int od = g_out_deg[idx];
            g_inv_src[idx]     = rsqrtf((float)(od > 0 ? od : 1));
        }
        __syncthreads();
        if (tid == 0) carry += total;
        __syncthreads();
    }
}

__global__ void k_fill(const int* __restrict__ src, const int* __restrict__ dst, int E) {
    GRID_WAIT();
    int e = blockIdx.x * blockDim.x + threadIdx.x;
    if (e < E) {
        int p = atomicAdd(&g_cursor[dst[e]], 1);
        g_col[p] = src[e];
    }
}

// ---------------- fused converter (features + weights -> fp16) ----------------
struct ConvArgs { const float* feat; const float* w[7]; };

__global__ void k_convert_all(ConvArgs a) {
    GRID_WAIT();
    int i = blockIdx.x * blockDim.x + threadIdx.x;
    if (i < FEAT_N) {
        g_x[i] = __float2half_rn(a.feat[i]);
        return;
    }
    int j = i - FEAT_N;
    if (j >= W_TOTAL) return;
    const int starts[7] = {0, 196608, 344064, 442368, 507904, 540672, 557056};
    int seg = 0;
#pragma unroll
    for (int k = 1; k < 7; ++k) seg += (j >= starts[k]) ? 1 : 0;
    g_w[j] = __float2half_rn(a.w[seg][j - starts[seg]]);
}

// ---------------- aggregation: one WARP per dst node, wide fp16 gathers ------
// GC=false (SAGE): out_i = relu((sum y_s + y_i) * inv_den_i + b)
// GC=true  (GCN) : out_i = relu(inv_dst_i * sum y'_s + b),  y' = inv_src*y
template <int DIM, bool GC>
__global__ void k_agg(const __half* __restrict__ y, __half* __restrict__ x,
                      const float* __restrict__ bias) {
    GRID_WAIT();
    const int gwarp = (blockIdx.x * blockDim.x + threadIdx.x) >> 5;
    if (gwarp >= N_NODES) return;
    const int lane = threadIdx.x & 31;
    constexpr bool H8 = (DIM >= 256);
    constexpr bool H4 = (DIM == 384) || (DIM == 128);
    constexpr int  B4 = (DIM == 384) ? 256 : 0;

    float a8[H8 ? 8 : 1];
    float a4[H4 ? 4 : 1];
#pragma unroll
    for (int q = 0; q < (H8 ? 8 : 1); ++q) a8[q] = 0.f;
#pragma unroll
    for (int q = 0; q < (H4 ? 4 : 1); ++q) a4[q] = 0.f;

    const int start = g_row_ptr[gwarp];
    const int end   = g_row_ptr[gwarp + 1];

    auto accum_row = [&](int s) {
        const __half* yr = y + (size_t)s * DIM;
        if (H8) {
            uint4 v = *(const uint4*)(yr + lane * 8);
            const __half2* p = (const __half2*)&v;
#pragma unroll
            for (int q = 0; q < 4; ++q) {
                float2 f = __half22float2(p[q]);
                a8[q * 2]     += f.x;
                a8[q * 2 + 1] += f.y;
            }
        }
        if (H4) {
            uint2 v = *(const uint2*)(yr + B4 + lane * 4);
            const __half2* p = (const __half2*)&v;
#pragma unroll
            for (int q = 0; q < 2; ++q) {
                float2 f = __half22float2(p[q]);
                a4[q * 2]     += f.x;
                a4[q * 2 + 1] += f.y;
            }
        }
    };

    int e = start;
    for (; e + 1 < end; e += 2) {
        const int s0 = g_col[e];
        const int s1 = g_col[e + 1];
        accum_row(s0);
        accum_row(s1);
    }
    if (e < end) accum_row(g_col[e]);

    GRID_TRIGGER();   // gathers done; let the next GEMM stage its launch

    __half* xr = x + (size_t)gwarp * DIM;
    const __half* yi = y + (size_t)gwarp * DIM;
    const float wsc = GC ? g_inv_dst[gwarp] : g_inv_den[gwarp];

    if (H8) {
        float o[8];
        if (GC) {
#pragma unroll
            for (int q = 0; q < 8; ++q)
                o[q] = fmaxf(a8[q] * wsc + bias[lane * 8 + q], 0.f);
        } else {
            uint4 v = *(const uint4*)(yi + lane * 8);
            const __half2* p = (const __half2*)&v;
#pragma unroll
            for (int q = 0; q < 4; ++q) {
                float2 f = __half22float2(p[q]);
                o[q * 2]     = fmaxf((a8[q * 2]     + f.x) * wsc + bias[lane * 8 + q * 2],     0.f);
                o[q * 2 + 1] = fmaxf((a8[q * 2 + 1] + f.y) * wsc + bias[lane * 8 + q * 2 + 1], 0.f);
            }
        }
        __half2 pk[4];
#pragma unroll
        for (int q = 0; q < 4; ++q) pk[q] = __floats2half2_rn(o[q * 2], o[q * 2 + 1]);
        *(uint4*)(xr + lane * 8) = *(const uint4*)pk;
    }
    if (H4) {
        float o[4];
        if (GC) {
#pragma unroll
            for (int q = 0; q < 4; ++q)
                o[q] = fmaxf(a4[q] * wsc + bias[B4 + lane * 4 + q], 0.f);
        } else {
            uint2 v = *(const uint2*)(yi + B4 + lane * 4);
            const __half2* p = (const __half2*)&v;
#pragma unroll
            for (int q = 0; q < 2; ++q) {
                float2 f = __half22float2(p[q]);
                o[q * 2]     = fmaxf((a4[q * 2]     + f.x) * wsc + bias[B4 + lane * 4 + q * 2],     0.f);
                o[q * 2 + 1] = fmaxf((a4[q * 2 + 1] + f.y) * wsc + bias[B4 + lane * 4 + q * 2 + 1], 0.f);
            }
        }
        __half2 pk[2];
#pragma unroll
        for (int q = 0; q < 2; ++q) pk[q] = __floats2half2_rn(o[q * 2], o[q * 2 + 1]);
        *(uint2*)(xr + B4 + lane * 4) = *(const uint2*)pk;
    }
}

// ---------------- plain fp16 HMMA GEMM ----------------------------------------
// C = A[M,K] @ W[Nc,K]^T (fp32 accum).  Single product (W rounded to fp16).
// 3-stage cp.async pipeline, ONE __syncthreads per k-chunk, 2 CTAs/SM.
#define T_A   0
#define T_B   16384
#define STAGE_BYTES 32768
#define NSTAGE 3
#define GEMM_SMEM (STAGE_BYTES * NSTAGE)

__global__ __launch_bounds__(256, 2)
void k_gemm_mma(const __half* __restrict__ A, const __half* __restrict__ W,
                const float* __restrict__ bias, const float* __restrict__ rowscale,
                __half* __restrict__ Ch, float* __restrict__ Cf, int M, int K, int Nc) {
    GRID_WAIT();
    extern __shared__ char sm[];
    const uint32_t sb = smem_u32(sm);
    const int tid  = threadIdx.x;
    const int wid  = tid >> 5;
    const int lane = tid & 31;
    const int wm = wid >> 2;
    const int wn = wid & 3;
    const int m0 = blockIdx.y * 128;
    const int n0 = blockIdx.x * 128;

    float acc[4][4][4];
#pragma unroll
    for (int i = 0; i < 4; ++i)
#pragma unroll
        for (int j = 0; j < 4; ++j)
#pragma unroll
            for (int q = 0; q < 4; ++q) acc[i][j][q] = 0.f;

    const int nch = K >> 6;

    auto issue = [&](int ch) {
        const uint32_t so = sb + (uint32_t)(ch % NSTAGE) * STAGE_BYTES;
        const int kc0 = ch << 6;
#pragma unroll
        for (int it = 0; it < 4; ++it) {
            const int idx = tid + it * 256;      // 0..1023
            const int r = idx >> 3, c = idx & 7;
            const uint32_t sw = (uint32_t)(r * 128 + (((c ^ (r & 7)) & 7) << 4));
            const int gr = m0 + r;
            const int av = (gr < M) ? 16 : 0;
            cp16(so + T_A + sw, A + (size_t)gr * K + kc0 + c * 8, av);
            cp16(so + T_B + sw, W + (size_t)(n0 + r) * K + kc0 + c * 8, 16);
        }
        asm volatile("cp.async.commit_group;" ::: "memory");
    };

    issue(0);
    if (nch > 1) issue(1);

    for (int ch = 0; ch < nch; ++ch) {
        if (ch + 2 <= nch) {
            asm volatile("cp.async.wait_group 1;" ::: "memory");
        } else {
            asm volatile("cp.async.wait_group 0;" ::: "memory");
        }
        __syncthreads();   // single barrier per chunk (3-stage safety)

        const uint32_t so = sb + (uint32_t)(ch % NSTAGE) * STAGE_BYTES;
#pragma unroll
        for (int kk = 0; kk < 64; kk += 16) {
            uint32_t af[4][4];
            const int ar = (lane & 15);
            const int akb = kk + ((lane >> 4) << 3);
#pragma unroll
            for (int mi = 0; mi < 4; ++mi) {
                const int r = wm * 64 + mi * 16 + ar;
                const uint32_t off = (uint32_t)(r * 128 + ((((akb >> 3) ^ (r & 7)) & 7) << 4));
                ldsm4(af[mi], so + T_A + off);
            }
            uint32_t bf[2][4];
            const int br = ((lane >> 4) << 3) + (lane & 7);
            const int bkb = kk + (((lane >> 3) & 1) << 3);
#pragma unroll
            for (int p = 0; p < 2; ++p) {
                const int r = wn * 32 + p * 16 + br;
                const uint32_t off = (uint32_t)(r * 128 + ((((bkb >> 3) ^ (r & 7)) & 7) << 4));
                ldsm4(bf[p], so + T_B + off);
            }
#pragma unroll
            for (int mi = 0; mi < 4; ++mi) {
#pragma unroll
                for (int j = 0; j < 4; ++j) {
                    mma16816h(acc[mi][j], af[mi], &bf[j >> 1][(j & 1) * 2]);
                }
            }
        }

        if (ch + 2 < nch) issue(ch + 2);
    }

    GRID_TRIGGER();   // mainloop done; stage the dependent launch during epilogue

    // ---- epilogue ----
    const int gid  = lane >> 2;
    const int tidx = lane & 3;
#pragma unroll
    for (int mi = 0; mi < 4; ++mi) {
        const int row = m0 + wm * 64 + mi * 16 + gid;
        float sc0 = 1.f, sc1 = 1.f;
        if (rowscale) {
            if (row < M)     sc0 = rowscale[row];
            if (row + 8 < M) sc1 = rowscale[row + 8];
        }
#pragma unroll
        for (int j = 0; j < 4; ++j) {
            const int col = n0 + wn * 32 + j * 8 + tidx * 2;
            if (Ch) {
                if (row < M)
                    *(__half2*)(Ch + (size_t)row * Nc + col) =
                        __floats2half2_rn(acc[mi][j][0] * sc0, acc[mi][j][1] * sc0);
                if (row + 8 < M)
                    *(__half2*)(Ch + (size_t)(row + 8) * Nc + col) =
                        __floats2half2_rn(acc[mi][j][2] * sc1, acc[mi][j][3] * sc1);
            } else {
                float b0 = 0.f, b1 = 0.f;
                if (bias) { b0 = bias[col]; b1 = bias[col + 1]; }
                if (row < M)
                    *(float2*)(Cf + (size_t)row * Nc + col) =
                        make_float2(acc[mi][j][0] + b0, acc[mi][j][1] + b1);
                if (row + 8 < M)
                    *(float2*)(Cf + (size_t)(row + 8) * Nc + col) =
                        make_float2(acc[mi][j][2] + b0, acc[mi][j][3] + b1);
            }
        }
    }
}

// ---------------- PDL launch helper -------------------------------------------
template <typename... Args>
static inline void launch_pdl(void (*kern)(Args...), dim3 grid, dim3 block,
                              size_t smem, Args... args) {
    cudaLaunchConfig_t cfg = {};
    cfg.gridDim = grid;
    cfg.blockDim = block;
    cfg.dynamicSmemBytes = smem;
    cfg.stream = 0;
    cudaLaunchAttribute attr[1];
    attr[0].id = cudaLaunchAttributeProgrammaticStreamSerialization;
    attr[0].val.programmaticStreamSerializationAllowed = 1;
    cfg.attrs = attr;
    cfg.numAttrs = 1;
    cudaLaunchKernelEx(&cfg, kern, args...);
}

// ---------------- host orchestration -----------------------------------------
static inline void launch_gemm_h(const __half* A, const __half* w,
                                 const float* rowscale, __half* Ch, int K, int Nc) {
    dim3 grid(Nc / 128, (N_NODES + 127) / 128);
    launch_pdl(k_gemm_mma, grid, dim3(256), (size_t)GEMM_SMEM,
               A, w, (const float*)nullptr, rowscale, Ch, (float*)nullptr,
               (int)N_NODES, K, Nc);
}
static inline void launch_gemm_f(const __half* A, const __half* w,
                                 const float* b, float* Cf, int K, int Nc) {
    dim3 grid(Nc / 128, (N_NODES + 127) / 128);
    launch_pdl(k_gemm_mma, grid, dim3(256), (size_t)GEMM_SMEM,
               A, w, b, (const float*)nullptr, (__half*)nullptr, Cf,
               (int)N_NODES, K, Nc);
}

template <int DIM, bool GC>
static inline void launch_agg(const __half* y, __half* x, const float* bias) {
    int blocks = (N_NODES + 7) / 8;
    launch_pdl(k_agg<DIM, GC>, dim3(blocks), dim3(256), (size_t)0, y, x, bias);
}

extern "C" void kernel_launch(void* const* d_in, const int* in_sizes, int n_in,
                              void* d_out, int out_size) {
    const float* features = (const float*)d_in[0];
    const int*   src      = (const int*)d_in[1];
    const int*   dst      = (const int*)d_in[2];
    const float* sw0 = (const float*)d_in[3];  const float* sb0 = (const float*)d_in[4];
    const float* gw0 = (const float*)d_in[5];  const float* gb0 = (const float*)d_in[6];
    const float* sw1 = (const float*)d_in[7];  const float* sb1 = (const float*)d_in[8];
    const float* gw1 = (const float*)d_in[9];  const float* gb1 = (const float*)d_in[10];
    const float* sw2 = (const float*)d_in[11]; const float* sb2 = (const float*)d_in[12];
    const float* gw2 = (const float*)d_in[13]; const float* gb2 = (const float*)d_in[14];
    const float* fcw = (const float*)d_in[15]; const float* fcb = (const float*)d_in[16];
    const int E = in_sizes[1];

    cudaFuncSetAttribute(k_gemm_mma, cudaFuncAttributeMaxDynamicSharedMemorySize, GEMM_SMEM);

    __half *ybuf = nullptr, *xbuf = nullptr, *wbuf = nullptr;
    float* inv_src = nullptr;
    cudaGetSymbolAddress((void**)&ybuf, g_y);
    cudaGetSymbolAddress((void**)&xbuf, g_x);
    cudaGetSymbolAddress((void**)&wbuf, g_w);
    cudaGetSymbolAddress((void**)&inv_src, g_inv_src);

    const int O_SW0 = 0,      O_GW0 = 196608, O_SW1 = 344064, O_GW1 = 442368;
    const int O_SW2 = 507904, O_GW2 = 540672, O_FC  = 557056;

    // ---- CSR build ----
    launch_pdl(k_zero_deg, dim3((N_NODES + 255) / 256), dim3(256), (size_t)0);
    launch_pdl(k_count, dim3((E + 255) / 256), dim3(256), (size_t)0, src, dst, E);
    launch_pdl(k_scan, dim3(1), dim3(1024), (size_t)0);
    launch_pdl(k_fill, dim3((E + 255) / 256), dim3(256), (size_t)0, src, dst, E);

    // ---- fused converts ----
    ConvArgs ca;
    ca.feat = features;
    ca.w[0] = sw0; ca.w[1] = gw0; ca.w[2] = sw1; ca.w[3] = gw1;
    ca.w[4] = sw2; ca.w[5] = gw2; ca.w[6] = fcw;
    launch_pdl(k_convert_all, dim3((FEAT_N + W_TOTAL + 255) / 256), dim3(256), (size_t)0, ca);

    // ---- stage 0: 512 -> 384 ----
    launch_gemm_h(xbuf, wbuf + O_SW0, nullptr, ybuf, 512, 384);
    launch_agg<384, false>(ybuf, xbuf, sb0);
    launch_gemm_h(xbuf, wbuf + O_GW0, inv_src, ybuf, 384, 384);
    launch_agg<384, true>(ybuf, xbuf, gb0);

    // ---- stage 1: 384 -> 256 ----
    launch_gemm_h(xbuf, wbuf + O_SW1, nullptr, ybuf, 384, 256);
    launch_agg<256, false>(ybuf, xbuf, sb1);
    launch_gemm_h(xbuf, wbuf + O_GW1, inv_src, ybuf, 256, 256);
    launch_agg<256, true>(ybuf, xbuf, gb1);

    // ---- stage 2: 256 -> 128 ----
    launch_gemm_h(xbuf, wbuf + O_SW2, nullptr, ybuf, 256, 128);
    launch_agg<128, false>(ybuf, xbuf, sb2);
    launch_gemm_h(xbuf, wbuf + O_GW2, inv_src, ybuf, 128, 128);
    launch_agg<128, true>(ybuf, xbuf, gb2);

    // ---- final FC: 128 -> 128 (fp32 out, bias, no relu) ----
    launch_gemm_f(xbuf, wbuf + O_FC, fcb, (float*)d_out, 128, 128);
}